// round 6
// baseline (speedup 1.0000x reference)
#include <cuda_runtime.h>
#include <cstdint>

#define BD   512
#define DD   256
#define NPIX 65536

// -0.5 * log2(e): exp(-0.5*m) == exp2f(NHL2E * m)
#define NHL2E (-0.72134752044448170f)

__device__ float    g_part[BD * 4];
__device__ unsigned g_cnt [BD];     // zero-init; self-resetting each run
__device__ unsigned g_cnt2[BD];

__device__ __forceinline__ uint32_t smem_u32(const void* p) {
    uint32_t a;
    asm("{ .reg .u64 t; cvta.to.shared.u64 t, %1; cvt.u32.u64 %0, t; }"
        : "=r"(a) : "l"(p));
    return a;
}

// ---------------------------------------------------------------------------
// One fused kernel. grid(BD*4), block(256). Block (b, q) owns quarter-row q
// (z-slices [4q,4q+4), 16384 px = 64 KB) of gaussian row b.
// Phases: params GEMV -> per-line vertex precompute -> exp into smem (+ partial
// sum) -> cross-block sum handshake -> scale smem -> TMA bulk store.
// ---------------------------------------------------------------------------
__global__ void __launch_bounds__(256) fused_kernel(
        const float* __restrict__ rep,
        const float* __restrict__ mw,
        const float* __restrict__ mb,
        const float* __restrict__ sw,
        const float* __restrict__ sb,
        float* __restrict__ out) {
    extern __shared__ float4 buf[];            // 4096 float4 = 64 KB
    __shared__ float sdots[8][9];
    __shared__ float spar[12];
    __shared__ float s_kv[256], s_cl[256];
    __shared__ float ssum[8];
    __shared__ float sinv;

    int b = blockIdx.x >> 2;
    int q = blockIdx.x & 3;
    int t = threadIdx.x;
    int wid = t >> 5, lane = t & 31;

    // ---- phase 1: params (9-dot GEMV over DD=256, replicated per block) ----
    {
        float r = rep[b * DD + t];
        float a0 = r * mw[0 * DD + t];
        float a1 = r * mw[1 * DD + t];
        float a2 = r * mw[2 * DD + t];
        float a3 = r * sw[0 * DD + t];
        float a4 = r * sw[1 * DD + t];
        float a5 = r * sw[2 * DD + t];
        float a6 = r * sw[3 * DD + t];
        float a7 = r * sw[4 * DD + t];
        float a8 = r * sw[5 * DD + t];
        #pragma unroll
        for (int o = 16; o; o >>= 1) {
            a0 += __shfl_down_sync(~0u, a0, o);
            a1 += __shfl_down_sync(~0u, a1, o);
            a2 += __shfl_down_sync(~0u, a2, o);
            a3 += __shfl_down_sync(~0u, a3, o);
            a4 += __shfl_down_sync(~0u, a4, o);
            a5 += __shfl_down_sync(~0u, a5, o);
            a6 += __shfl_down_sync(~0u, a6, o);
            a7 += __shfl_down_sync(~0u, a7, o);
            a8 += __shfl_down_sync(~0u, a8, o);
        }
        if (lane == 0) {
            sdots[wid][0] = a0; sdots[wid][1] = a1; sdots[wid][2] = a2;
            sdots[wid][3] = a3; sdots[wid][4] = a4; sdots[wid][5] = a5;
            sdots[wid][6] = a6; sdots[wid][7] = a7; sdots[wid][8] = a8;
        }
    }
    __syncthreads();

    if (t == 0) {
        float d[9];
        #pragma unroll
        for (int j = 0; j < 9; j++) {
            float acc = 0.f;
            #pragma unroll
            for (int w8 = 0; w8 < 8; w8++) acc += sdots[w8][j];
            d[j] = acc;
        }
        float m0 = d[0] + mb[0];
        float m1 = d[1] + mb[1];
        float m2 = d[2] + mb[2];
        float e[6];
        #pragma unroll
        for (int j = 0; j < 6; j++) {
            float x = d[3 + j] + sb[j];
            e[j] = (x > 0.f) ? (x + 1.f) : __expf(x);      // elu + 1
        }
        float l00 = e[0] + log1pf(__expf(-e[0]));          // softplus
        float l11 = e[2] + log1pf(__expf(-e[2]));
        float l22 = e[5] + log1pf(__expf(-e[5]));
        float i00 = 1.f / l00, i11 = 1.f / l11, i22 = 1.f / l22;
        float l10 = e[1], l20 = e[3], l21 = e[4];
        float dz1 = -l10 * i00 * i11;
        float dz2 = (-l20 * i00 - l21 * dz1) * i22;
        float h   = i00 * i00 + dz1 * dz1 + dz2 * dz2;     // x-curvature (>0)

        spar[0] = m0;  spar[1] = m1;  spar[2] = m2;
        spar[3] = i00; spar[4] = i11; spar[5] = i22;
        spar[6] = l10; spar[7] = l20; spar[8] = l21;
        spar[9] = dz1; spar[10] = dz2;
        spar[11] = NHL2E * h;                              // nh
    }
    __syncthreads();

    float m0 = spar[0], m1 = spar[1], m2 = spar[2];
    float i00 = spar[3], i11 = spar[4], i22 = spar[5];
    float l10 = spar[6], l20 = spar[7], l21 = spar[8];
    float dz1 = spar[9], dz2 = spar[10], nh = spar[11];

    // ---- phase 2: per-line vertex form. Line t of this quarter (256 lines).
    // maha(k) = h*(k - kv)^2 + mmin, k = x index 0..63.
    {
        int yi = t & 63;
        int zi = (q << 2) + (t >> 6);
        float d1 = ((float)yi - 31.5f) - m1;
        float d2 = ((float)zi - 7.5f)  - m2;
        float z0 = (-31.5f - m0) * i00;                    // at k = 0
        float z1 = (d1 - l10 * z0) * i11;
        float z2 = (d2 - l20 * z0 - l21 * z1) * i22;
        float beta  = 2.f * (z0 * i00 + z1 * dz1 + z2 * dz2);
        float gamma = z0 * z0 + z1 * z1 + z2 * z2;
        float h     = i00 * i00 + dz1 * dz1 + dz2 * dz2;
        float kv    = beta * (-0.5f / h);
        float mmin  = fmaf(0.5f * beta, kv, gamma);        // gamma - beta^2/(4h)
        s_kv[t] = kv;
        s_cl[t] = NHL2E * mmin;
    }
    __syncthreads();

    // ---- phase 3: exps into smem + partial sum. Iter j: 4 consecutive px at
    // position j*1024 + t*4 within the quarter (coalesced STS.128).
    float sum = 0.f;
    #pragma unroll
    for (int j = 0; j < 16; j++) {
        int line = (j << 4) + (t >> 4);
        float kv = s_kv[line];
        float cl = s_cl[line];
        float tt = (float)((t & 15) << 2) - kv;
        float4 v;
        float a;
        a = tt * tt; v.x = exp2f(fmaf(a, nh, cl)); tt += 1.f;
        a = tt * tt; v.y = exp2f(fmaf(a, nh, cl)); tt += 1.f;
        a = tt * tt; v.z = exp2f(fmaf(a, nh, cl)); tt += 1.f;
        a = tt * tt; v.w = exp2f(fmaf(a, nh, cl));
        sum += (v.x + v.y) + (v.z + v.w);
        buf[(j << 8) + t] = v;
    }

    // block reduction of partial sum
    #pragma unroll
    for (int o = 16; o; o >>= 1) sum += __shfl_down_sync(~0u, sum, o);
    if (lane == 0) ssum[wid] = sum;
    __syncthreads();

    // ---- phase 4: cross-block handshake (4 blocks per row) ----
    if (t == 0) {
        float s2 = 0.f;
        #pragma unroll
        for (int w8 = 0; w8 < 8; w8++) s2 += ssum[w8];
        g_part[blockIdx.x] = s2;
        __threadfence();
        atomicAdd(&g_cnt[b], 1u);
        const volatile unsigned* vc = g_cnt + b;
        while (*vc < 4u) __nanosleep(64);
        __threadfence();
        const volatile float* gp = g_part + (b << 2);
        float tot = (gp[0] + gp[1]) + (gp[2] + gp[3]);     // fixed order: deterministic
        sinv = 1.f / tot;                                  // eps dropped: <=1e-10 rel
        unsigned o2 = atomicAdd(&g_cnt2[b], 1u);
        if (o2 == 3u) {                                    // last reader resets for next run
            g_cnt[b] = 0u;
            g_cnt2[b] = 0u;
            __threadfence();
        }
    }
    __syncthreads();

    // ---- phase 5: scale smem in place ----
    float inv = sinv;
    #pragma unroll
    for (int j = 0; j < 16; j++) {
        float4 v = buf[(j << 8) + t];
        v.x *= inv; v.y *= inv; v.z *= inv; v.w *= inv;
        buf[(j << 8) + t] = v;
    }
    __syncthreads();

    // ---- phase 6: TMA bulk store 64 KB smem -> gmem ----
    if (t == 0) {
        asm volatile("fence.proxy.async;" ::: "memory");
        uint32_t sptr = smem_u32(buf);
        float* gdst = out + ((size_t)b << 16) + (q << 14);
        #pragma unroll
        for (int c = 0; c < 4; c++) {
            asm volatile(
                "cp.async.bulk.global.shared::cta.bulk_group [%0], [%1], %2;"
                :: "l"(gdst + (c << 12)), "r"(sptr + (c << 14)), "r"(16384)
                : "memory");
        }
        asm volatile("cp.async.bulk.commit_group;" ::: "memory");
        asm volatile("cp.async.bulk.wait_group 0;" ::: "memory");  // keep smem alive
    }
}

// ---------------------------------------------------------------------------
extern "C" void kernel_launch(void* const* d_in, const int* in_sizes, int n_in,
                              void* d_out, int out_size) {
    const float* rep = (const float*)d_in[0];   // [512,256]
    const float* mw  = (const float*)d_in[1];   // [3,256]
    const float* mb  = (const float*)d_in[2];   // [3]
    const float* sw  = (const float*)d_in[3];   // [6,256]
    const float* sb  = (const float*)d_in[4];   // [6]
    // d_in[5] = pixel_positions: analytic grid, recomputed on the fly
    float* out = (float*)d_out;                 // [512, 65536]

    static bool attr_done = false;
    if (!attr_done) {
        cudaFuncSetAttribute(fused_kernel,
                             cudaFuncAttributeMaxDynamicSharedMemorySize, 65536);
        attr_done = true;
    }
    fused_kernel<<<BD * 4, 256, 65536>>>(rep, mw, mb, sw, sb, out);
}

// round 8
// speedup vs baseline: 1.2653x; 1.2653x over previous
#include <cuda_runtime.h>
#include <cstdint>

#define BD   512
#define DD   256
#define NPIX 65536

// -0.5 * log2(e): exp(-0.5*m) == exp2f(NHL2E * m)
#define NHL2E (-0.72134752044448170f)
#define CUT   (-126.0f)

// m0,m1,m2, i00,i11,i22, l10,l20,l21, dz1,dz2, nh
__device__ float g_params[BD * 12];
__device__ float g_part[BD * 4];

__device__ __forceinline__ uint32_t smem_u32(const void* p) {
    uint32_t a;
    asm("{ .reg .u64 t; cvta.to.shared.u64 t, %1; cvt.u32.u64 %0, t; }"
        : "=r"(a) : "l"(p));
    return a;
}

// Per-line vertex-form setup: maha(k) = h*(k-kv)^2 + mmin along x.
// Anchored at k0=round(kv) (clamped) to avoid cancellation in mmin.
__device__ __forceinline__ void line_vertex(
        float yi, float zi,
        float m0, float m1, float m2,
        float i00, float i11, float i22,
        float l10, float l20, float l21,
        float dz1, float dz2, float h,
        float& kv, float& cl /* = NHL2E*mmin */) {
    float d1 = (yi - 31.5f) - m1;
    float d2 = (zi - 7.5f)  - m2;
    float z0 = (-31.5f - m0) * i00;              // at k = 0
    float z1 = (d1 - l10 * z0) * i11;
    float z2 = (d2 - l20 * z0 - l21 * z1) * i22;
    float beta = 2.f * (z0 * i00 + z1 * dz1 + z2 * dz2);
    kv = beta * (-0.5f / h);
    float k0 = fminf(63.f, fmaxf(0.f, rintf(kv)));
    float z0a = fmaf(k0, i00, z0);
    float z1a = fmaf(k0, dz1, z1);
    float z2a = fmaf(k0, dz2, z2);
    float ma  = fmaf(z0a, z0a, fmaf(z1a, z1a, z2a * z2a));  // exact maha(k0)
    float o0  = k0 - kv;                                    // |o0| small when kv in-grid
    cl = NHL2E * fmaf(-h, o0 * o0, ma);
}

// ---------------------------------------------------------------------------
// Kernel 1: params GEMV (replicated per row-quarter) + quarter-row sum of
// exp2(nh*(k-kv)^2 + cl) over only the active x-range per line.
// grid(BD*4), block(256): thread t owns line t (64 px) of its quarter.
// ---------------------------------------------------------------------------
__global__ void __launch_bounds__(256) reduce_kernel(
        const float* __restrict__ rep,
        const float* __restrict__ mw,
        const float* __restrict__ mb,
        const float* __restrict__ sw,
        const float* __restrict__ sb) {
    int b = blockIdx.x >> 2;
    int s = blockIdx.x & 3;
    int t = threadIdx.x;
    int wid = t >> 5, lane = t & 31;

    __shared__ float sdots[8][9];
    __shared__ float spar[12];

    // ---- params phase ----
    {
        float r = rep[b * DD + t];
        float a0 = r * mw[0 * DD + t];
        float a1 = r * mw[1 * DD + t];
        float a2 = r * mw[2 * DD + t];
        float a3 = r * sw[0 * DD + t];
        float a4 = r * sw[1 * DD + t];
        float a5 = r * sw[2 * DD + t];
        float a6 = r * sw[3 * DD + t];
        float a7 = r * sw[4 * DD + t];
        float a8 = r * sw[5 * DD + t];
        #pragma unroll
        for (int o = 16; o; o >>= 1) {
            a0 += __shfl_down_sync(~0u, a0, o);
            a1 += __shfl_down_sync(~0u, a1, o);
            a2 += __shfl_down_sync(~0u, a2, o);
            a3 += __shfl_down_sync(~0u, a3, o);
            a4 += __shfl_down_sync(~0u, a4, o);
            a5 += __shfl_down_sync(~0u, a5, o);
            a6 += __shfl_down_sync(~0u, a6, o);
            a7 += __shfl_down_sync(~0u, a7, o);
            a8 += __shfl_down_sync(~0u, a8, o);
        }
        if (lane == 0) {
            sdots[wid][0] = a0; sdots[wid][1] = a1; sdots[wid][2] = a2;
            sdots[wid][3] = a3; sdots[wid][4] = a4; sdots[wid][5] = a5;
            sdots[wid][6] = a6; sdots[wid][7] = a7; sdots[wid][8] = a8;
        }
    }
    __syncthreads();

    if (t == 0) {
        float d[9];
        #pragma unroll
        for (int j = 0; j < 9; j++) {
            float acc = 0.f;
            #pragma unroll
            for (int w8 = 0; w8 < 8; w8++) acc += sdots[w8][j];
            d[j] = acc;
        }
        float m0 = d[0] + mb[0];
        float m1 = d[1] + mb[1];
        float m2 = d[2] + mb[2];
        float e[6];
        #pragma unroll
        for (int j = 0; j < 6; j++) {
            float x = d[3 + j] + sb[j];
            e[j] = (x > 0.f) ? (x + 1.f) : __expf(x);      // elu + 1
        }
        float l00 = e[0] + log1pf(__expf(-e[0]));          // softplus
        float l11 = e[2] + log1pf(__expf(-e[2]));
        float l22 = e[5] + log1pf(__expf(-e[5]));
        float i00 = 1.f / l00, i11 = 1.f / l11, i22 = 1.f / l22;
        float l10 = e[1], l20 = e[3], l21 = e[4];
        float dz1 = -l10 * i00 * i11;
        float dz2 = (-l20 * i00 - l21 * dz1) * i22;
        float h   = i00 * i00 + dz1 * dz1 + dz2 * dz2;

        spar[0] = m0;  spar[1] = m1;  spar[2] = m2;
        spar[3] = i00; spar[4] = i11; spar[5] = i22;
        spar[6] = l10; spar[7] = l20; spar[8] = l21;
        spar[9] = dz1; spar[10] = dz2;
        spar[11] = NHL2E * h;                              // nh (< 0)
    }
    __syncthreads();

    if (s == 0 && t < 12) g_params[b * 12 + t] = spar[t];

    float m0 = spar[0], m1 = spar[1], m2 = spar[2];
    float i00 = spar[3], i11 = spar[4], i22 = spar[5];
    float l10 = spar[6], l20 = spar[7], l21 = spar[8];
    float dz1 = spar[9], dz2 = spar[10], nh = spar[11];
    float h = nh * (1.0f / NHL2E);

    // ---- per-line vertex + active-range sum ----
    float yi = (float)(t & 63);
    float zi = (float)((s << 2) + (t >> 6));
    float kv, cl;
    line_vertex(yi, zi, m0, m1, m2, i00, i11, i22,
                l10, l20, l21, dz1, dz2, h, kv, cl);

    float sum = 0.f;
    float rsq = (CUT - cl) / nh;       // (k-kv)^2 <= rsq is the active range
    if (rsq > 0.f) {
        float R = fminf(sqrtf(rsq), 96.f);
        int klo = max(0,  (int)ceilf(kv - R));
        int khi = min(63, (int)floorf(kv + R));
        float tt = (float)klo - kv;
        #pragma unroll 4
        for (int k = klo; k <= khi; k++) {
            sum += exp2f(fmaf(tt * tt, nh, cl));
            tt += 1.f;
        }
    }

    // block reduction
    #pragma unroll
    for (int o = 16; o; o >>= 1) sum += __shfl_down_sync(~0u, sum, o);
    __shared__ float ssum[8];
    if (lane == 0) ssum[wid] = sum;
    __syncthreads();
    if (t == 0) {
        float s2 = 0.f;
        #pragma unroll
        for (int w8 = 0; w8 < 8; w8++) s2 += ssum[w8];
        g_part[blockIdx.x] = s2;       // eps dropped: <=1e-10 rel effect
    }
}

// ---------------------------------------------------------------------------
// Kernel 2: normalized probabilities via smem + TMA bulk stores.
// grid(BD*4), block(256): quarter row per block, 4 double-buffered 16 KB
// chunks. 1/sum folded into the exp2 argument; inactive 4-px groups are
// zero-filled without touching MUFU.
// ---------------------------------------------------------------------------
__global__ void __launch_bounds__(256) write_kernel(float* __restrict__ out) {
    __shared__ float4 buf[2][1024];    // 2 x 16 KB
    __shared__ float spar[12];
    __shared__ float s_lg;
    __shared__ float s_kv[256], s_c2[256];

    int b = blockIdx.x >> 2;
    int q = blockIdx.x & 3;
    int t = threadIdx.x;

    if (t < 12) spar[t] = g_params[b * 12 + t];
    if (t == 32) {
        const float* gp = g_part + (b << 2);
        float s2 = (gp[0] + gp[1]) + (gp[2] + gp[3]);   // fixed order
        s_lg = -log2f(s2);
    }
    __syncthreads();

    float m0 = spar[0], m1 = spar[1], m2 = spar[2];
    float i00 = spar[3], i11 = spar[4], i22 = spar[5];
    float l10 = spar[6], l20 = spar[7], l21 = spar[8];
    float dz1 = spar[9], dz2 = spar[10], nh = spar[11];
    float h = nh * (1.0f / NHL2E);
    float lg = s_lg;

    // per-line vertex precompute (line t of this quarter)
    {
        float yi = (float)(t & 63);
        float zi = (float)((q << 2) + (t >> 6));
        float kv, cl;
        line_vertex(yi, zi, m0, m1, m2, i00, i11, i22,
                    l10, l20, l21, dz1, dz2, h, kv, cl);
        s_kv[t] = kv;
        s_c2[t] = cl + lg;             // normalized-domain constant
    }
    __syncthreads();

    float* gdst_row = out + ((size_t)b << 16) + (q << 14);

    for (int c = 0; c < 4; c++) {
        int bi = c & 1;
        if (c >= 2) {
            if (t == 0)
                asm volatile("cp.async.bulk.wait_group 1;" ::: "memory");
            __syncthreads();           // buffer bi reusable
        }
        #pragma unroll
        for (int k = 0; k < 4; k++) {
            int idx  = (k << 8) + t;                   // float4 slot in chunk
            int line = (c << 6) + (k << 4) + (t >> 4); // line within quarter
            float kv = s_kv[line];
            float c2 = s_c2[line];
            float tt = (float)((t & 15) << 2) - kv;    // offset of 1st px
            // nearest |offset| within this 4-px group
            float tn = (tt > 0.f) ? tt : ((tt + 3.f < 0.f) ? (tt + 3.f) : 0.f);
            float4 v = make_float4(0.f, 0.f, 0.f, 0.f);
            if (fmaf(tn * tn, nh, c2) > -130.f) {      // group active?
                float a;
                a = tt * tt; v.x = exp2f(fmaf(a, nh, c2)); tt += 1.f;
                a = tt * tt; v.y = exp2f(fmaf(a, nh, c2)); tt += 1.f;
                a = tt * tt; v.z = exp2f(fmaf(a, nh, c2)); tt += 1.f;
                a = tt * tt; v.w = exp2f(fmaf(a, nh, c2));
            }
            buf[bi][idx] = v;
        }
        __syncthreads();
        if (t == 0) {
            asm volatile("fence.proxy.async;" ::: "memory");
            uint32_t sptr = smem_u32(&buf[bi][0]);
            asm volatile(
                "cp.async.bulk.global.shared::cta.bulk_group [%0], [%1], %2;"
                :: "l"(gdst_row + (c << 12)), "r"(sptr), "r"(16384)
                : "memory");
            asm volatile("cp.async.bulk.commit_group;" ::: "memory");
        }
    }
    if (t == 0)
        asm volatile("cp.async.bulk.wait_group 0;" ::: "memory");
}

// ---------------------------------------------------------------------------
extern "C" void kernel_launch(void* const* d_in, const int* in_sizes, int n_in,
                              void* d_out, int out_size) {
    const float* rep = (const float*)d_in[0];   // [512,256]
    const float* mw  = (const float*)d_in[1];   // [3,256]
    const float* mb  = (const float*)d_in[2];   // [3]
    const float* sw  = (const float*)d_in[3];   // [6,256]
    const float* sb  = (const float*)d_in[4];   // [6]
    // d_in[5] = pixel_positions: analytic grid, recomputed on the fly
    float* out = (float*)d_out;                 // [512, 65536]

    reduce_kernel<<<BD * 4, 256>>>(rep, mw, mb, sw, sb);
    write_kernel<<<BD * 4, 256>>>(out);
}

// round 10
// speedup vs baseline: 1.4053x; 1.1106x over previous
#include <cuda_runtime.h>
#include <cstdint>

#define BD   512
#define DD   256
#define NPIX 65536

// -0.5 * log2(e): exp(-0.5*m) == exp2f(NHL2E * m)
#define NHL2E (-0.72134752044448170f)
#define CUT   (-126.0f)

// m0,m1,m2, i00,i11,i22, l10,l20,l21, dz1,dz2, nh
__device__ float g_params[BD * 12];
__device__ float g_part[BD * 2];

__device__ __forceinline__ uint32_t smem_u32(const void* p) {
    uint32_t a;
    asm("{ .reg .u64 t; cvta.to.shared.u64 t, %1; cvt.u32.u64 %0, t; }"
        : "=r"(a) : "l"(p));
    return a;
}

// Per-line vertex form: maha(k) = h*(k-kv)^2 + mmin along x.
// Anchored at k0=round(kv) (clamped) to avoid cancellation in mmin.
__device__ __forceinline__ void line_vertex(
        float yi, float zi,
        float m0, float m1, float m2,
        float i00, float i11, float i22,
        float l10, float l20, float l21,
        float dz1, float dz2, float h,
        float& kv, float& cl /* = NHL2E*mmin */) {
    float d1 = (yi - 31.5f) - m1;
    float d2 = (zi - 7.5f)  - m2;
    float z0 = (-31.5f - m0) * i00;              // at k = 0
    float z1 = (d1 - l10 * z0) * i11;
    float z2 = (d2 - l20 * z0 - l21 * z1) * i22;
    float beta = 2.f * (z0 * i00 + z1 * dz1 + z2 * dz2);
    kv = beta * (-0.5f / h);
    float k0 = fminf(63.f, fmaxf(0.f, rintf(kv)));
    float z0a = fmaf(k0, i00, z0);
    float z1a = fmaf(k0, dz1, z1);
    float z2a = fmaf(k0, dz2, z2);
    float ma  = fmaf(z0a, z0a, fmaf(z1a, z1a, z2a * z2a));  // exact maha(k0)
    float o0  = k0 - kv;
    cl = NHL2E * fmaf(-h, o0 * o0, ma);
}

// ---------------------------------------------------------------------------
// Kernel 1: params GEMV (replicated 2x per row) + half-row sum of
// exp2(nh*(k-kv)^2 + cl) over active x-ranges only.
// grid(BD*2), block(256): thread t owns lines t and t+256 of its half
// (z-slices [8s, 8s+8)).
// ---------------------------------------------------------------------------
__global__ void __launch_bounds__(256) reduce_kernel(
        const float* __restrict__ rep,
        const float* __restrict__ mw,
        const float* __restrict__ mb,
        const float* __restrict__ sw,
        const float* __restrict__ sb) {
    int b = blockIdx.x >> 1;
    int s = blockIdx.x & 1;
    int t = threadIdx.x;
    int wid = t >> 5, lane = t & 31;

    __shared__ float sdots[8][9];
    __shared__ float spar[12];

    // ---- params phase ----
    {
        float r = rep[b * DD + t];
        float a0 = r * mw[0 * DD + t];
        float a1 = r * mw[1 * DD + t];
        float a2 = r * mw[2 * DD + t];
        float a3 = r * sw[0 * DD + t];
        float a4 = r * sw[1 * DD + t];
        float a5 = r * sw[2 * DD + t];
        float a6 = r * sw[3 * DD + t];
        float a7 = r * sw[4 * DD + t];
        float a8 = r * sw[5 * DD + t];
        #pragma unroll
        for (int o = 16; o; o >>= 1) {
            a0 += __shfl_down_sync(~0u, a0, o);
            a1 += __shfl_down_sync(~0u, a1, o);
            a2 += __shfl_down_sync(~0u, a2, o);
            a3 += __shfl_down_sync(~0u, a3, o);
            a4 += __shfl_down_sync(~0u, a4, o);
            a5 += __shfl_down_sync(~0u, a5, o);
            a6 += __shfl_down_sync(~0u, a6, o);
            a7 += __shfl_down_sync(~0u, a7, o);
            a8 += __shfl_down_sync(~0u, a8, o);
        }
        if (lane == 0) {
            sdots[wid][0] = a0; sdots[wid][1] = a1; sdots[wid][2] = a2;
            sdots[wid][3] = a3; sdots[wid][4] = a4; sdots[wid][5] = a5;
            sdots[wid][6] = a6; sdots[wid][7] = a7; sdots[wid][8] = a8;
        }
    }
    __syncthreads();

    if (t == 0) {
        float d[9];
        #pragma unroll
        for (int j = 0; j < 9; j++) {
            float acc = 0.f;
            #pragma unroll
            for (int w8 = 0; w8 < 8; w8++) acc += sdots[w8][j];
            d[j] = acc;
        }
        float m0 = d[0] + mb[0];
        float m1 = d[1] + mb[1];
        float m2 = d[2] + mb[2];
        float e[6];
        #pragma unroll
        for (int j = 0; j < 6; j++) {
            float x = d[3 + j] + sb[j];
            e[j] = (x > 0.f) ? (x + 1.f) : __expf(x);      // elu + 1
        }
        float l00 = e[0] + log1pf(__expf(-e[0]));          // softplus
        float l11 = e[2] + log1pf(__expf(-e[2]));
        float l22 = e[5] + log1pf(__expf(-e[5]));
        float i00 = 1.f / l00, i11 = 1.f / l11, i22 = 1.f / l22;
        float l10 = e[1], l20 = e[3], l21 = e[4];
        float dz1 = -l10 * i00 * i11;
        float dz2 = (-l20 * i00 - l21 * dz1) * i22;
        float h   = i00 * i00 + dz1 * dz1 + dz2 * dz2;

        spar[0] = m0;  spar[1] = m1;  spar[2] = m2;
        spar[3] = i00; spar[4] = i11; spar[5] = i22;
        spar[6] = l10; spar[7] = l20; spar[8] = l21;
        spar[9] = dz1; spar[10] = dz2;
        spar[11] = NHL2E * h;                              // nh (< 0)
    }
    __syncthreads();

    if (s == 0 && t < 12) g_params[b * 12 + t] = spar[t];

    float m0 = spar[0], m1 = spar[1], m2 = spar[2];
    float i00 = spar[3], i11 = spar[4], i22 = spar[5];
    float l10 = spar[6], l20 = spar[7], l21 = spar[8];
    float dz1 = spar[9], dz2 = spar[10], nh = spar[11];
    float h = nh * (1.0f / NHL2E);

    // ---- per-thread: 2 lines, active-range sums ----
    float sum = 0.f;
    #pragma unroll
    for (int li = 0; li < 2; li++) {
        int L = (li << 8) + t;                 // 0..511 within half
        float yi = (float)(L & 63);
        float zi = (float)((s << 3) + (L >> 6));
        float kv, cl;
        line_vertex(yi, zi, m0, m1, m2, i00, i11, i22,
                    l10, l20, l21, dz1, dz2, h, kv, cl);
        float rsq = (CUT - cl) / nh;           // (k-kv)^2 <= rsq active
        if (rsq > 0.f) {
            float R = fminf(sqrtf(rsq), 96.f);
            int klo = max(0,  (int)ceilf(kv - R));
            int khi = min(63, (int)floorf(kv + R));
            float tt = (float)klo - kv;
            #pragma unroll 4
            for (int k = klo; k <= khi; k++) {
                sum += exp2f(fmaf(tt * tt, nh, cl));
                tt += 1.f;
            }
        }
    }

    // block reduction
    #pragma unroll
    for (int o = 16; o; o >>= 1) sum += __shfl_down_sync(~0u, sum, o);
    __shared__ float ssum[8];
    if (lane == 0) ssum[wid] = sum;
    __syncthreads();
    if (t == 0) {
        float s2 = 0.f;
        #pragma unroll
        for (int w8 = 0; w8 < 8; w8++) s2 += ssum[w8];
        g_part[blockIdx.x] = s2;               // eps dropped: <=1e-10 rel
    }
}

// ---------------------------------------------------------------------------
// Kernel 2: one 16 KB chunk (4096 px = 64 x-lines) per block, single TMA
// bulk store. grid(BD*16), block(256). 1/sum folded into exponent; inactive
// 4-px groups zero-filled without MUFU.
// ---------------------------------------------------------------------------
__global__ void __launch_bounds__(256) write_kernel(float* __restrict__ out) {
    __shared__ float4 buf[1024];               // 16 KB
    __shared__ float skv[64], scl[64];
    __shared__ float slg;

    int b = blockIdx.x >> 4;
    int c = blockIdx.x & 15;                   // chunk within row
    int t = threadIdx.x;

    float nh = g_params[b * 12 + 11];          // broadcast (L2-cached)
    float h  = nh * (1.0f / NHL2E);

    // phase A: 64 line vertices + normalizer
    if (t < 64) {
        const float* P = g_params + b * 12;
        float m0 = P[0], m1 = P[1], m2 = P[2];
        float i00 = P[3], i11 = P[4], i22 = P[5];
        float l10 = P[6], l20 = P[7], l21 = P[8];
        float dz1 = P[9], dz2 = P[10];
        int L = (c << 6) + t;                  // global line in row
        float yi = (float)(L & 63);
        float zi = (float)(L >> 6);
        float kv, cl;
        line_vertex(yi, zi, m0, m1, m2, i00, i11, i22,
                    l10, l20, l21, dz1, dz2, h, kv, cl);
        skv[t] = kv;
        scl[t] = cl;
    } else if (t == 64) {
        float s2 = g_part[b * 2] + g_part[b * 2 + 1];   // fixed order
        slg = -log2f(s2);
    }
    __syncthreads();

    // phase B: fill 16 KB chunk (4 float4 per thread, conflict-free STS.128)
    float lg = slg;
    #pragma unroll
    for (int k = 0; k < 4; k++) {
        int idx  = (k << 8) + t;               // float4 slot, 0..1023
        int line = idx >> 4;                   // 0..63
        float kv = skv[line];
        float c2 = scl[line] + lg;
        float tt = (float)((t & 15) << 2) - kv;
        float tn = (tt > 0.f) ? tt : ((tt + 3.f < 0.f) ? (tt + 3.f) : 0.f);
        float4 v = make_float4(0.f, 0.f, 0.f, 0.f);
        if (fmaf(tn * tn, nh, c2) > -130.f) {
            float a;
            a = tt * tt; v.x = exp2f(fmaf(a, nh, c2)); tt += 1.f;
            a = tt * tt; v.y = exp2f(fmaf(a, nh, c2)); tt += 1.f;
            a = tt * tt; v.z = exp2f(fmaf(a, nh, c2)); tt += 1.f;
            a = tt * tt; v.w = exp2f(fmaf(a, nh, c2));
        }
        buf[idx] = v;
    }
    __syncthreads();

    // phase C: single bulk store
    if (t == 0) {
        asm volatile("fence.proxy.async;" ::: "memory");
        uint32_t sptr = smem_u32(buf);
        float* gdst = out + ((size_t)b << 16) + (c << 12);
        asm volatile(
            "cp.async.bulk.global.shared::cta.bulk_group [%0], [%1], %2;"
            :: "l"(gdst), "r"(sptr), "r"(16384) : "memory");
        asm volatile("cp.async.bulk.commit_group;" ::: "memory");
        asm volatile("cp.async.bulk.wait_group 0;" ::: "memory");
    }
}

// ---------------------------------------------------------------------------
extern "C" void kernel_launch(void* const* d_in, const int* in_sizes, int n_in,
                              void* d_out, int out_size) {
    const float* rep = (const float*)d_in[0];   // [512,256]
    const float* mw  = (const float*)d_in[1];   // [3,256]
    const float* mb  = (const float*)d_in[2];   // [3]
    const float* sw  = (const float*)d_in[3];   // [6,256]
    const float* sb  = (const float*)d_in[4];   // [6]
    // d_in[5] = pixel_positions: analytic grid, recomputed on the fly
    float* out = (float*)d_out;                 // [512, 65536]

    reduce_kernel<<<BD * 2, 256>>>(rep, mw, mb, sw, sb);
    write_kernel<<<BD * 16, 256>>>(out);
}